// round 1
// baseline (speedup 1.0000x reference)
#include <cuda_runtime.h>
#include <math.h>

#define B_  4
#define T_  2048
#define D_  1024
#define H_  16
#define DH_ 64
#define FF_ 4096
#define NT  (B_*T_)   // 8192

// ---------------- scratch (static device globals; no allocation) ----------------
__device__ float g_h  [(size_t)NT*D_];
__device__ float g_q  [(size_t)NT*D_];
__device__ float g_k  [(size_t)NT*D_];
__device__ float g_v  [(size_t)NT*D_];
__device__ float g_att[(size_t)NT*D_];
__device__ float g_x2 [(size_t)NT*D_];
__device__ float g_ff [(size_t)NT*FF_];

// ---------------- LayerNorm: one block per row (D=1024, 256 thr x 4) ----------------
__global__ void __launch_bounds__(256) ln_k(const float* __restrict__ x,
                                            const float* __restrict__ g,
                                            const float* __restrict__ b,
                                            float* __restrict__ out)
{
    __shared__ float red[2][8];
    int row = blockIdx.x;
    int tid = threadIdx.x;
    const float* xr = x + (size_t)row * D_;
    int c = tid * 4;
    float4 xv = *(const float4*)(xr + c);
    float s  = xv.x + xv.y + xv.z + xv.w;
    float ss = xv.x*xv.x + xv.y*xv.y + xv.z*xv.z + xv.w*xv.w;
    #pragma unroll
    for (int o = 16; o > 0; o >>= 1) {
        s  += __shfl_down_sync(0xffffffffu, s,  o);
        ss += __shfl_down_sync(0xffffffffu, ss, o);
    }
    if ((tid & 31) == 0) { red[0][tid >> 5] = s; red[1][tid >> 5] = ss; }
    __syncthreads();
    if (tid < 32) {
        s  = (tid < 8) ? red[0][tid] : 0.f;
        ss = (tid < 8) ? red[1][tid] : 0.f;
        #pragma unroll
        for (int o = 4; o > 0; o >>= 1) {
            s  += __shfl_down_sync(0xffffffffu, s,  o);
            ss += __shfl_down_sync(0xffffffffu, ss, o);
        }
        if (tid == 0) { red[0][0] = s; red[1][0] = ss; }
    }
    __syncthreads();
    float mean = red[0][0] * (1.f / D_);
    float var  = red[1][0] * (1.f / D_) - mean * mean;
    float rstd = rsqrtf(var + 1e-5f);
    float4 gv = *(const float4*)(g + c);
    float4 bv = *(const float4*)(b + c);
    float4 ov;
    ov.x = (xv.x - mean) * rstd * gv.x + bv.x;
    ov.y = (xv.y - mean) * rstd * gv.y + bv.y;
    ov.z = (xv.z - mean) * rstd * gv.z + bv.z;
    ov.w = (xv.w - mean) * rstd * gv.w + bv.w;
    *(float4*)(out + (size_t)row * D_ + c) = ov;
}

// ---------------- SGEMM: C[M,N] = A[M,K] @ W[N,K]^T + bias (+res) (opt GELU) ----------------
// 128x128 tile, BK=8, 256 threads, 8x8 micro-tile. M,N,K all multiples of tile dims here.
template<bool GELU, bool RES>
__global__ void __launch_bounds__(256) sgemm_k(const float* __restrict__ A,
                                               const float* __restrict__ W,
                                               const float* __restrict__ bias,
                                               const float* __restrict__ res,
                                               float* __restrict__ C,
                                               int M, int N, int K)
{
    __shared__ float As[8][128];
    __shared__ float Bs[8][128];
    int tid = threadIdx.x;
    int m0 = blockIdx.y * 128;
    int n0 = blockIdx.x * 128;
    int lr = tid >> 1;          // 0..127
    int lc = (tid & 1) * 4;     // 0 or 4
    const float* Ag = A + (size_t)(m0 + lr) * K + lc;
    const float* Wg = W + (size_t)(n0 + lr) * K + lc;
    int ty = tid >> 4, tx = tid & 15;
    float acc[8][8];
    #pragma unroll
    for (int i = 0; i < 8; i++)
        #pragma unroll
        for (int j = 0; j < 8; j++) acc[i][j] = 0.f;

    for (int k0 = 0; k0 < K; k0 += 8) {
        float4 a4 = *(const float4*)(Ag + k0);
        float4 b4 = *(const float4*)(Wg + k0);
        As[lc + 0][lr] = a4.x; As[lc + 1][lr] = a4.y;
        As[lc + 2][lr] = a4.z; As[lc + 3][lr] = a4.w;
        Bs[lc + 0][lr] = b4.x; Bs[lc + 1][lr] = b4.y;
        Bs[lc + 2][lr] = b4.z; Bs[lc + 3][lr] = b4.w;
        __syncthreads();
        #pragma unroll
        for (int kk = 0; kk < 8; kk++) {
            float a[8], bb[8];
            *(float4*)(a)      = *(const float4*)&As[kk][ty * 8];
            *(float4*)(a + 4)  = *(const float4*)&As[kk][ty * 8 + 4];
            *(float4*)(bb)     = *(const float4*)&Bs[kk][tx * 8];
            *(float4*)(bb + 4) = *(const float4*)&Bs[kk][tx * 8 + 4];
            #pragma unroll
            for (int i = 0; i < 8; i++)
                #pragma unroll
                for (int j = 0; j < 8; j++)
                    acc[i][j] += a[i] * bb[j];
        }
        __syncthreads();
    }

    #pragma unroll
    for (int i = 0; i < 8; i++) {
        int row = m0 + ty * 8 + i;
        float* Cp = C + (size_t)row * N + n0 + tx * 8;
        const float* Rp = RES ? (res + (size_t)row * N + n0 + tx * 8) : (const float*)0;
        float v[8];
        #pragma unroll
        for (int j = 0; j < 8; j++) {
            float vv = acc[i][j] + bias[n0 + tx * 8 + j];
            if (RES) vv += Rp[j];
            if (GELU) vv = vv * normcdff(vv);
            v[j] = vv;
        }
        *(float4*)(Cp)     = make_float4(v[0], v[1], v[2], v[3]);
        *(float4*)(Cp + 4) = make_float4(v[4], v[5], v[6], v[7]);
    }
}

// ---------------- Flash attention: 64-query tile per CTA, loop K/V in 64-tiles ----------------
#define PADQ 68
#define PADS 65
__global__ void __launch_bounds__(256) flash_k(const float* __restrict__ q,
                                               const float* __restrict__ k,
                                               const float* __restrict__ v,
                                               float* __restrict__ o)
{
    extern __shared__ float sm[];
    float* Qs   = sm;                   // [64][PADQ]  (r, d), pre-scaled by 1/8
    float* Kst  = Qs  + 64 * PADQ;      // [64][PADQ]  (d, c)  transposed
    float* Vs   = Kst + 64 * PADQ;      // [64][PADQ]  (j, c)
    float* Ss   = Vs  + 64 * PADQ;      // [64][PADS]  scores -> probs
    float* s_m  = Ss  + 64 * PADS;      // [64]
    float* s_l  = s_m + 64;             // [64]
    float* s_al = s_l + 64;             // [64]

    int tid = threadIdx.x;
    int bh = blockIdx.y;
    int b  = bh >> 4;
    int h  = bh & 15;
    int qt0 = blockIdx.x * 64;
    size_t base = ((size_t)b * T_) * D_ + (size_t)h * DH_;

    // load Q tile (scaled by 1/sqrt(DH) = 0.125)
    {
        int r  = tid >> 2;
        int d0 = (tid & 3) * 16;
        const float* qp = q + base + (size_t)(qt0 + r) * D_ + d0;
        #pragma unroll
        for (int u = 0; u < 4; u++) {
            float4 t4 = *(const float4*)(qp + 4 * u);
            t4.x *= 0.125f; t4.y *= 0.125f; t4.z *= 0.125f; t4.w *= 0.125f;
            *(float4*)&Qs[r * PADQ + d0 + 4 * u] = t4;
        }
    }
    if (tid < 64) { s_m[tid] = -1e30f; s_l[tid] = 0.f; }

    float acc[4][4];
    #pragma unroll
    for (int i = 0; i < 4; i++)
        #pragma unroll
        for (int j = 0; j < 4; j++) acc[i][j] = 0.f;

    int ty = tid >> 4, tx = tid & 15;

    for (int kt0 = 0; kt0 < T_; kt0 += 64) {
        __syncthreads();
        // load K (transposed) and V tiles
        {
            int r  = tid >> 2;
            int d0 = (tid & 3) * 16;
            const float* kp = k + base + (size_t)(kt0 + r) * D_ + d0;
            const float* vp = v + base + (size_t)(kt0 + r) * D_ + d0;
            #pragma unroll
            for (int u = 0; u < 4; u++) {
                float4 kv = *(const float4*)(kp + 4 * u);
                Kst[(d0 + 4 * u + 0) * PADQ + r] = kv.x;
                Kst[(d0 + 4 * u + 1) * PADQ + r] = kv.y;
                Kst[(d0 + 4 * u + 2) * PADQ + r] = kv.z;
                Kst[(d0 + 4 * u + 3) * PADQ + r] = kv.w;
                *(float4*)&Vs[r * PADQ + d0 + 4 * u] = *(const float4*)(vp + 4 * u);
            }
        }
        __syncthreads();

        // S = Qs @ Kst  (rows 4ty.., cols 4tx..)
        float s4[4][4];
        #pragma unroll
        for (int i = 0; i < 4; i++)
            #pragma unroll
            for (int j = 0; j < 4; j++) s4[i][j] = 0.f;
        #pragma unroll 8
        for (int d = 0; d < 64; d++) {
            float a0 = Qs[(4 * ty + 0) * PADQ + d];
            float a1 = Qs[(4 * ty + 1) * PADQ + d];
            float a2 = Qs[(4 * ty + 2) * PADQ + d];
            float a3 = Qs[(4 * ty + 3) * PADQ + d];
            float4 kv = *(const float4*)&Kst[d * PADQ + 4 * tx];
            s4[0][0] += a0 * kv.x; s4[0][1] += a0 * kv.y; s4[0][2] += a0 * kv.z; s4[0][3] += a0 * kv.w;
            s4[1][0] += a1 * kv.x; s4[1][1] += a1 * kv.y; s4[1][2] += a1 * kv.z; s4[1][3] += a1 * kv.w;
            s4[2][0] += a2 * kv.x; s4[2][1] += a2 * kv.y; s4[2][2] += a2 * kv.z; s4[2][3] += a2 * kv.w;
            s4[3][0] += a3 * kv.x; s4[3][1] += a3 * kv.y; s4[3][2] += a3 * kv.z; s4[3][3] += a3 * kv.w;
        }
        #pragma unroll
        for (int i = 0; i < 4; i++)
            #pragma unroll
            for (int j = 0; j < 4; j++)
                Ss[(4 * ty + i) * PADS + 4 * tx + j] = s4[i][j];
        __syncthreads();

        // online softmax: 4 threads per row, 16 cols each
        {
            int r  = tid >> 2;
            int jl = (tid & 3) * 16;
            float mt = -1e30f;
            #pragma unroll
            for (int jj = 0; jj < 16; jj++) mt = fmaxf(mt, Ss[r * PADS + jl + jj]);
            mt = fmaxf(mt, __shfl_xor_sync(0xffffffffu, mt, 1));
            mt = fmaxf(mt, __shfl_xor_sync(0xffffffffu, mt, 2));
            float mo = s_m[r];
            float mn = fmaxf(mo, mt);
            float ps = 0.f;
            #pragma unroll
            for (int jj = 0; jj < 16; jj++) {
                float p = __expf(Ss[r * PADS + jl + jj] - mn);
                Ss[r * PADS + jl + jj] = p;
                ps += p;
            }
            ps += __shfl_xor_sync(0xffffffffu, ps, 1);
            ps += __shfl_xor_sync(0xffffffffu, ps, 2);
            if ((tid & 3) == 0) {
                float al = __expf(mo - mn);
                s_l[r] = s_l[r] * al + ps;
                s_m[r] = mn;
                s_al[r] = al;
            }
        }
        __syncthreads();

        // O = O*alpha + P @ V
        #pragma unroll
        for (int i = 0; i < 4; i++) {
            float al = s_al[4 * ty + i];
            float c0 = acc[i][0] * al, c1 = acc[i][1] * al;
            float c2 = acc[i][2] * al, c3 = acc[i][3] * al;
            const float* Sr = &Ss[(4 * ty + i) * PADS];
            #pragma unroll 8
            for (int j = 0; j < 64; j++) {
                float p = Sr[j];
                float4 vv = *(const float4*)&Vs[j * PADQ + 4 * tx];
                c0 += p * vv.x; c1 += p * vv.y; c2 += p * vv.z; c3 += p * vv.w;
            }
            acc[i][0] = c0; acc[i][1] = c1; acc[i][2] = c2; acc[i][3] = c3;
        }
    }
    __syncthreads();

    #pragma unroll
    for (int i = 0; i < 4; i++) {
        int r = 4 * ty + i;
        float inv = 1.f / s_l[r];
        float4 ov = make_float4(acc[i][0] * inv, acc[i][1] * inv,
                                acc[i][2] * inv, acc[i][3] * inv);
        *(float4*)&o[base + (size_t)(qt0 + r) * D_ + 4 * tx] = ov;
    }
}

// ---------------- launch ----------------
extern "C" void kernel_launch(void* const* d_in, const int* in_sizes, int n_in,
                              void* d_out, int out_size)
{
    const float* x    = (const float*)d_in[0];
    const float* ln1g = (const float*)d_in[1];
    const float* ln1b = (const float*)d_in[2];
    const float* ln2g = (const float*)d_in[3];
    const float* ln2b = (const float*)d_in[4];
    const float* wq   = (const float*)d_in[5];
    const float* bq   = (const float*)d_in[6];
    const float* wk   = (const float*)d_in[7];
    const float* bk   = (const float*)d_in[8];
    const float* wv   = (const float*)d_in[9];
    const float* bv   = (const float*)d_in[10];
    const float* wo   = (const float*)d_in[11];
    const float* bo   = (const float*)d_in[12];
    const float* w1   = (const float*)d_in[13];
    const float* b1   = (const float*)d_in[14];
    const float* w2   = (const float*)d_in[15];
    const float* b2   = (const float*)d_in[16];
    float* out = (float*)d_out;

    void* p;
    cudaGetSymbolAddress(&p, g_h);   float* h   = (float*)p;
    cudaGetSymbolAddress(&p, g_q);   float* qb  = (float*)p;
    cudaGetSymbolAddress(&p, g_k);   float* kb  = (float*)p;
    cudaGetSymbolAddress(&p, g_v);   float* vb  = (float*)p;
    cudaGetSymbolAddress(&p, g_att); float* att = (float*)p;
    cudaGetSymbolAddress(&p, g_x2);  float* x2  = (float*)p;
    cudaGetSymbolAddress(&p, g_ff);  float* ff  = (float*)p;

    int flash_smem = (3 * 64 * PADQ + 64 * PADS + 3 * 64) * (int)sizeof(float);
    cudaFuncSetAttribute(flash_k, cudaFuncAttributeMaxDynamicSharedMemorySize, flash_smem);

    dim3 gD(D_ / 128, NT / 128);    // (8, 64)
    dim3 gF(FF_ / 128, NT / 128);   // (32, 64)

    // h = LN1(x)
    ln_k<<<NT, 256>>>(x, ln1g, ln1b, h);
    // Q, K, V
    sgemm_k<false, false><<<gD, 256>>>(h, wq, bq, nullptr, qb, NT, D_, D_);
    sgemm_k<false, false><<<gD, 256>>>(h, wk, bk, nullptr, kb, NT, D_, D_);
    sgemm_k<false, false><<<gD, 256>>>(h, wv, bv, nullptr, vb, NT, D_, D_);
    // attention
    flash_k<<<dim3(T_ / 64, B_ * H_), 256, flash_smem>>>(qb, kb, vb, att);
    // x2 = x + att @ Wo^T + bo
    sgemm_k<false, true><<<gD, 256>>>(att, wo, bo, x, x2, NT, D_, D_);
    // h = LN2(x2)
    ln_k<<<NT, 256>>>(x2, ln2g, ln2b, h);
    // ff = gelu(h @ W1^T + b1)
    sgemm_k<true, false><<<gF, 256>>>(h, w1, b1, nullptr, ff, NT, FF_, D_);
    // out = x2 + ff @ W2^T + b2
    sgemm_k<false, true><<<gD, 256>>>(ff, w2, b2, x2, out, NT, D_, FF_);
}

// round 2
// speedup vs baseline: 1.7523x; 1.7523x over previous
#include <cuda_runtime.h>
#include <math.h>

#define B_  4
#define T_  2048
#define D_  1024
#define H_  16
#define DH_ 64
#define FF_ 4096
#define NT  (B_*T_)   // 8192

// ---------------- scratch (static device globals; no allocation) ----------------
__device__ float g_h  [(size_t)NT*D_];
__device__ float g_q  [(size_t)NT*D_];
__device__ float g_k  [(size_t)NT*D_];
__device__ float g_v  [(size_t)NT*D_];
__device__ float g_att[(size_t)NT*D_];
__device__ float g_x2 [(size_t)NT*D_];
__device__ float g_ff [(size_t)NT*FF_];

// ---------------- LayerNorm ----------------
__global__ void __launch_bounds__(256) ln_k(const float* __restrict__ x,
                                            const float* __restrict__ g,
                                            const float* __restrict__ b,
                                            float* __restrict__ out)
{
    __shared__ float red[2][8];
    int row = blockIdx.x;
    int tid = threadIdx.x;
    const float* xr = x + (size_t)row * D_;
    int c = tid * 4;
    float4 xv = *(const float4*)(xr + c);
    float s  = xv.x + xv.y + xv.z + xv.w;
    float ss = xv.x*xv.x + xv.y*xv.y + xv.z*xv.z + xv.w*xv.w;
    #pragma unroll
    for (int o = 16; o > 0; o >>= 1) {
        s  += __shfl_down_sync(0xffffffffu, s,  o);
        ss += __shfl_down_sync(0xffffffffu, ss, o);
    }
    if ((tid & 31) == 0) { red[0][tid >> 5] = s; red[1][tid >> 5] = ss; }
    __syncthreads();
    if (tid < 32) {
        s  = (tid < 8) ? red[0][tid] : 0.f;
        ss = (tid < 8) ? red[1][tid] : 0.f;
        #pragma unroll
        for (int o = 4; o > 0; o >>= 1) {
            s  += __shfl_down_sync(0xffffffffu, s,  o);
            ss += __shfl_down_sync(0xffffffffu, ss, o);
        }
        if (tid == 0) { red[0][0] = s; red[1][0] = ss; }
    }
    __syncthreads();
    float mean = red[0][0] * (1.f / D_);
    float var  = red[1][0] * (1.f / D_) - mean * mean;
    float rstd = rsqrtf(var + 1e-5f);
    float4 gv = *(const float4*)(g + c);
    float4 bv = *(const float4*)(b + c);
    float4 ov;
    ov.x = (xv.x - mean) * rstd * gv.x + bv.x;
    ov.y = (xv.y - mean) * rstd * gv.y + bv.y;
    ov.z = (xv.z - mean) * rstd * gv.z + bv.z;
    ov.w = (xv.w - mean) * rstd * gv.w + bv.w;
    *(float4*)(out + (size_t)row * D_ + c) = ov;
}

// ---------------- tf32 helpers ----------------
__device__ __forceinline__ unsigned f2tf(float x) {
    unsigned r;
    asm("cvt.rna.tf32.f32 %0, %1;" : "=r"(r) : "f"(x));
    return r;
}

__device__ __forceinline__ void mma_tf32(float4& c,
                                         unsigned a0, unsigned a1, unsigned a2, unsigned a3,
                                         unsigned b0, unsigned b1)
{
    asm volatile("mma.sync.aligned.m16n8k8.row.col.f32.tf32.tf32.f32 "
                 "{%0,%1,%2,%3}, {%4,%5,%6,%7}, {%8,%9}, {%0,%1,%2,%3};"
                 : "+f"(c.x), "+f"(c.y), "+f"(c.z), "+f"(c.w)
                 : "r"(a0), "r"(a1), "r"(a2), "r"(a3), "r"(b0), "r"(b1));
}

// ---------------- tf32 tensor-core GEMM: C[M,N] = A[M,K] @ W[N,K]^T + bias (+res)(gelu) ----
// 128x128 block tile, BK=32, 256 threads (8 warps as 2x4), warp tile 64x32,
// 16x m16n8k8 mma per warp per k8-step. smem row stride 36 words (conflict-free frags).
#define SPAD 36
template<bool GELU, bool RES>
__global__ void __launch_bounds__(256) mma_gemm(const float* __restrict__ A,
                                                const float* __restrict__ W,
                                                const float* __restrict__ bias,
                                                const float* __restrict__ res,
                                                float* __restrict__ C,
                                                int M, int N, int K)
{
    __shared__ unsigned As[128 * SPAD];
    __shared__ unsigned Bs[128 * SPAD];

    int tid  = threadIdx.x;
    int warp = tid >> 5;
    int lane = tid & 31;
    int g = lane >> 2;       // 0..7
    int t = lane & 3;        // 0..3
    int wm = (warp >> 2) * 64;   // 0 or 64
    int wn = (warp & 3) * 32;    // 0..96

    int m0 = blockIdx.y * 128;
    int n0 = blockIdx.x * 128;

    // staging coords: 1024 float4 per tile, 4 per thread
    int lrow[4], lc4[4];
    #pragma unroll
    for (int u = 0; u < 4; u++) {
        int lin = tid + u * 256;
        lrow[u] = lin >> 3;
        lc4[u]  = (lin & 7) * 4;
    }

    float4 acc[4][4];
    #pragma unroll
    for (int i = 0; i < 4; i++)
        #pragma unroll
        for (int j = 0; j < 4; j++) acc[i][j] = make_float4(0.f, 0.f, 0.f, 0.f);

    float4 stA[4], stB[4];
    // preload first tile
    #pragma unroll
    for (int u = 0; u < 4; u++) {
        stA[u] = *(const float4*)(A + (size_t)(m0 + lrow[u]) * K + lc4[u]);
        stB[u] = *(const float4*)(W + (size_t)(n0 + lrow[u]) * K + lc4[u]);
    }

    for (int k0 = 0; k0 < K; k0 += 32) {
        // regs -> smem (convert to tf32)
        #pragma unroll
        for (int u = 0; u < 4; u++) {
            unsigned* ap = &As[lrow[u] * SPAD + lc4[u]];
            ap[0] = f2tf(stA[u].x); ap[1] = f2tf(stA[u].y);
            ap[2] = f2tf(stA[u].z); ap[3] = f2tf(stA[u].w);
            unsigned* bp = &Bs[lrow[u] * SPAD + lc4[u]];
            bp[0] = f2tf(stB[u].x); bp[1] = f2tf(stB[u].y);
            bp[2] = f2tf(stB[u].z); bp[3] = f2tf(stB[u].w);
        }
        __syncthreads();

        // prefetch next tile
        if (k0 + 32 < K) {
            #pragma unroll
            for (int u = 0; u < 4; u++) {
                stA[u] = *(const float4*)(A + (size_t)(m0 + lrow[u]) * K + k0 + 32 + lc4[u]);
                stB[u] = *(const float4*)(W + (size_t)(n0 + lrow[u]) * K + k0 + 32 + lc4[u]);
            }
        }

        // compute
        #pragma unroll
        for (int kk = 0; kk < 32; kk += 8) {
            unsigned af[4][4];
            #pragma unroll
            for (int i = 0; i < 4; i++) {
                int r = wm + 16 * i + g;
                af[i][0] = As[r * SPAD + kk + t];
                af[i][1] = As[(r + 8) * SPAD + kk + t];
                af[i][2] = As[r * SPAD + kk + t + 4];
                af[i][3] = As[(r + 8) * SPAD + kk + t + 4];
            }
            unsigned bf[4][2];
            #pragma unroll
            for (int j = 0; j < 4; j++) {
                int cn = wn + 8 * j + g;
                bf[j][0] = Bs[cn * SPAD + kk + t];
                bf[j][1] = Bs[cn * SPAD + kk + t + 4];
            }
            #pragma unroll
            for (int i = 0; i < 4; i++)
                #pragma unroll
                for (int j = 0; j < 4; j++)
                    mma_tf32(acc[i][j], af[i][0], af[i][1], af[i][2], af[i][3],
                             bf[j][0], bf[j][1]);
        }
        __syncthreads();
    }

    // epilogue
    #pragma unroll
    for (int i = 0; i < 4; i++) {
        int r0 = m0 + wm + 16 * i + g;
        int r1 = r0 + 8;
        #pragma unroll
        for (int j = 0; j < 4; j++) {
            int col = n0 + wn + 8 * j + 2 * t;
            float b0 = bias[col], b1 = bias[col + 1];
            float v0 = acc[i][j].x + b0;
            float v1 = acc[i][j].y + b1;
            float v2 = acc[i][j].z + b0;
            float v3 = acc[i][j].w + b1;
            if (RES) {
                const float* rp0 = res + (size_t)r0 * N + col;
                const float* rp1 = res + (size_t)r1 * N + col;
                v0 += rp0[0]; v1 += rp0[1]; v2 += rp1[0]; v3 += rp1[1];
            }
            if (GELU) {
                v0 *= normcdff(v0); v1 *= normcdff(v1);
                v2 *= normcdff(v2); v3 *= normcdff(v3);
            }
            *(float2*)(C + (size_t)r0 * N + col) = make_float2(v0, v1);
            *(float2*)(C + (size_t)r1 * N + col) = make_float2(v2, v3);
        }
    }
}

// ---------------- Flash attention (fp32 SIMT, unchanged) ----------------
#define PADQ 68
#define PADS 65
__global__ void __launch_bounds__(256) flash_k(const float* __restrict__ q,
                                               const float* __restrict__ k,
                                               const float* __restrict__ v,
                                               float* __restrict__ o)
{
    extern __shared__ float sm[];
    float* Qs   = sm;
    float* Kst  = Qs  + 64 * PADQ;
    float* Vs   = Kst + 64 * PADQ;
    float* Ss   = Vs  + 64 * PADQ;
    float* s_m  = Ss  + 64 * PADS;
    float* s_l  = s_m + 64;
    float* s_al = s_l + 64;

    int tid = threadIdx.x;
    int bh = blockIdx.y;
    int b  = bh >> 4;
    int h  = bh & 15;
    int qt0 = blockIdx.x * 64;
    size_t base = ((size_t)b * T_) * D_ + (size_t)h * DH_;

    {
        int r  = tid >> 2;
        int d0 = (tid & 3) * 16;
        const float* qp = q + base + (size_t)(qt0 + r) * D_ + d0;
        #pragma unroll
        for (int u = 0; u < 4; u++) {
            float4 t4 = *(const float4*)(qp + 4 * u);
            t4.x *= 0.125f; t4.y *= 0.125f; t4.z *= 0.125f; t4.w *= 0.125f;
            *(float4*)&Qs[r * PADQ + d0 + 4 * u] = t4;
        }
    }
    if (tid < 64) { s_m[tid] = -1e30f; s_l[tid] = 0.f; }

    float acc[4][4];
    #pragma unroll
    for (int i = 0; i < 4; i++)
        #pragma unroll
        for (int j = 0; j < 4; j++) acc[i][j] = 0.f;

    int ty = tid >> 4, tx = tid & 15;

    for (int kt0 = 0; kt0 < T_; kt0 += 64) {
        __syncthreads();
        {
            int r  = tid >> 2;
            int d0 = (tid & 3) * 16;
            const float* kp = k + base + (size_t)(kt0 + r) * D_ + d0;
            const float* vp = v + base + (size_t)(kt0 + r) * D_ + d0;
            #pragma unroll
            for (int u = 0; u < 4; u++) {
                float4 kv = *(const float4*)(kp + 4 * u);
                Kst[(d0 + 4 * u + 0) * PADQ + r] = kv.x;
                Kst[(d0 + 4 * u + 1) * PADQ + r] = kv.y;
                Kst[(d0 + 4 * u + 2) * PADQ + r] = kv.z;
                Kst[(d0 + 4 * u + 3) * PADQ + r] = kv.w;
                *(float4*)&Vs[r * PADQ + d0 + 4 * u] = *(const float4*)(vp + 4 * u);
            }
        }
        __syncthreads();

        float s4[4][4];
        #pragma unroll
        for (int i = 0; i < 4; i++)
            #pragma unroll
            for (int j = 0; j < 4; j++) s4[i][j] = 0.f;
        #pragma unroll 8
        for (int d = 0; d < 64; d++) {
            float a0 = Qs[(4 * ty + 0) * PADQ + d];
            float a1 = Qs[(4 * ty + 1) * PADQ + d];
            float a2 = Qs[(4 * ty + 2) * PADQ + d];
            float a3 = Qs[(4 * ty + 3) * PADQ + d];
            float4 kv = *(const float4*)&Kst[d * PADQ + 4 * tx];
            s4[0][0] += a0 * kv.x; s4[0][1] += a0 * kv.y; s4[0][2] += a0 * kv.z; s4[0][3] += a0 * kv.w;
            s4[1][0] += a1 * kv.x; s4[1][1] += a1 * kv.y; s4[1][2] += a1 * kv.z; s4[1][3] += a1 * kv.w;
            s4[2][0] += a2 * kv.x; s4[2][1] += a2 * kv.y; s4[2][2] += a2 * kv.z; s4[2][3] += a2 * kv.w;
            s4[3][0] += a3 * kv.x; s4[3][1] += a3 * kv.y; s4[3][2] += a3 * kv.z; s4[3][3] += a3 * kv.w;
        }
        #pragma unroll
        for (int i = 0; i < 4; i++)
            #pragma unroll
            for (int j = 0; j < 4; j++)
                Ss[(4 * ty + i) * PADS + 4 * tx + j] = s4[i][j];
        __syncthreads();

        {
            int r  = tid >> 2;
            int jl = (tid & 3) * 16;
            float mt = -1e30f;
            #pragma unroll
            for (int jj = 0; jj < 16; jj++) mt = fmaxf(mt, Ss[r * PADS + jl + jj]);
            mt = fmaxf(mt, __shfl_xor_sync(0xffffffffu, mt, 1));
            mt = fmaxf(mt, __shfl_xor_sync(0xffffffffu, mt, 2));
            float mo = s_m[r];
            float mn = fmaxf(mo, mt);
            float ps = 0.f;
            #pragma unroll
            for (int jj = 0; jj < 16; jj++) {
                float p = __expf(Ss[r * PADS + jl + jj] - mn);
                Ss[r * PADS + jl + jj] = p;
                ps += p;
            }
            ps += __shfl_xor_sync(0xffffffffu, ps, 1);
            ps += __shfl_xor_sync(0xffffffffu, ps, 2);
            if ((tid & 3) == 0) {
                float al = __expf(mo - mn);
                s_l[r] = s_l[r] * al + ps;
                s_m[r] = mn;
                s_al[r] = al;
            }
        }
        __syncthreads();

        #pragma unroll
        for (int i = 0; i < 4; i++) {
            float al = s_al[4 * ty + i];
            float c0 = acc[i][0] * al, c1 = acc[i][1] * al;
            float c2 = acc[i][2] * al, c3 = acc[i][3] * al;
            const float* Sr = &Ss[(4 * ty + i) * PADS];
            #pragma unroll 8
            for (int j = 0; j < 64; j++) {
                float p = Sr[j];
                float4 vv = *(const float4*)&Vs[j * PADQ + 4 * tx];
                c0 += p * vv.x; c1 += p * vv.y; c2 += p * vv.z; c3 += p * vv.w;
            }
            acc[i][0] = c0; acc[i][1] = c1; acc[i][2] = c2; acc[i][3] = c3;
        }
    }
    __syncthreads();

    #pragma unroll
    for (int i = 0; i < 4; i++) {
        int r = 4 * ty + i;
        float inv = 1.f / s_l[r];
        float4 ov = make_float4(acc[i][0] * inv, acc[i][1] * inv,
                                acc[i][2] * inv, acc[i][3] * inv);
        *(float4*)&o[base + (size_t)(qt0 + r) * D_ + 4 * tx] = ov;
    }
}

// ---------------- launch ----------------
extern "C" void kernel_launch(void* const* d_in, const int* in_sizes, int n_in,
                              void* d_out, int out_size)
{
    const float* x    = (const float*)d_in[0];
    const float* ln1g = (const float*)d_in[1];
    const float* ln1b = (const float*)d_in[2];
    const float* ln2g = (const float*)d_in[3];
    const float* ln2b = (const float*)d_in[4];
    const float* wq   = (const float*)d_in[5];
    const float* bq   = (const float*)d_in[6];
    const float* wk   = (const float*)d_in[7];
    const float* bk   = (const float*)d_in[8];
    const float* wv   = (const float*)d_in[9];
    const float* bv   = (const float*)d_in[10];
    const float* wo   = (const float*)d_in[11];
    const float* bo   = (const float*)d_in[12];
    const float* w1   = (const float*)d_in[13];
    const float* b1   = (const float*)d_in[14];
    const float* w2   = (const float*)d_in[15];
    const float* b2   = (const float*)d_in[16];
    float* out = (float*)d_out;

    void* p;
    cudaGetSymbolAddress(&p, g_h);   float* h   = (float*)p;
    cudaGetSymbolAddress(&p, g_q);   float* qb  = (float*)p;
    cudaGetSymbolAddress(&p, g_k);   float* kb  = (float*)p;
    cudaGetSymbolAddress(&p, g_v);   float* vb  = (float*)p;
    cudaGetSymbolAddress(&p, g_att); float* att = (float*)p;
    cudaGetSymbolAddress(&p, g_x2);  float* x2  = (float*)p;
    cudaGetSymbolAddress(&p, g_ff);  float* ff  = (float*)p;

    int flash_smem = (3 * 64 * PADQ + 64 * PADS + 3 * 64) * (int)sizeof(float);
    cudaFuncSetAttribute(flash_k, cudaFuncAttributeMaxDynamicSharedMemorySize, flash_smem);

    dim3 gD(D_ / 128, NT / 128);    // (8, 64)
    dim3 gF(FF_ / 128, NT / 128);   // (32, 64)

    ln_k<<<NT, 256>>>(x, ln1g, ln1b, h);
    mma_gemm<false, false><<<gD, 256>>>(h, wq, bq, nullptr, qb, NT, D_, D_);
    mma_gemm<false, false><<<gD, 256>>>(h, wk, bk, nullptr, kb, NT, D_, D_);
    mma_gemm<false, false><<<gD, 256>>>(h, wv, bv, nullptr, vb, NT, D_, D_);
    flash_k<<<dim3(T_ / 64, B_ * H_), 256, flash_smem>>>(qb, kb, vb, att);
    mma_gemm<false, true><<<gD, 256>>>(att, wo, bo, x, x2, NT, D_, D_);
    ln_k<<<NT, 256>>>(x2, ln2g, ln2b, h);
    mma_gemm<true, false><<<gF, 256>>>(h, w1, b1, nullptr, ff, NT, FF_, D_);
    mma_gemm<false, true><<<gD, 256>>>(ff, w2, b2, x2, out, NT, D_, FF_);
}

// round 3
// speedup vs baseline: 3.9156x; 2.2345x over previous
#include <cuda_runtime.h>
#include <math.h>

#define B_  4
#define T_  2048
#define D_  1024
#define H_  16
#define DH_ 64
#define FF_ 4096
#define NT  (B_*T_)   // 8192

// ---------------- scratch (static device globals; no allocation) ----------------
__device__ float g_h  [(size_t)NT*D_];
__device__ float g_q  [(size_t)NT*D_];
__device__ float g_k  [(size_t)NT*D_];
__device__ float g_v  [(size_t)NT*D_];
__device__ float g_att[(size_t)NT*D_];
__device__ float g_x2 [(size_t)NT*D_];
__device__ float g_ff [(size_t)NT*FF_];

// ---------------- LayerNorm ----------------
__global__ void __launch_bounds__(256) ln_k(const float* __restrict__ x,
                                            const float* __restrict__ g,
                                            const float* __restrict__ b,
                                            float* __restrict__ out)
{
    __shared__ float red[2][8];
    int row = blockIdx.x;
    int tid = threadIdx.x;
    const float* xr = x + (size_t)row * D_;
    int c = tid * 4;
    float4 xv = *(const float4*)(xr + c);
    float s  = xv.x + xv.y + xv.z + xv.w;
    float ss = xv.x*xv.x + xv.y*xv.y + xv.z*xv.z + xv.w*xv.w;
    #pragma unroll
    for (int o = 16; o > 0; o >>= 1) {
        s  += __shfl_down_sync(0xffffffffu, s,  o);
        ss += __shfl_down_sync(0xffffffffu, ss, o);
    }
    if ((tid & 31) == 0) { red[0][tid >> 5] = s; red[1][tid >> 5] = ss; }
    __syncthreads();
    if (tid < 32) {
        s  = (tid < 8) ? red[0][tid] : 0.f;
        ss = (tid < 8) ? red[1][tid] : 0.f;
        #pragma unroll
        for (int o = 4; o > 0; o >>= 1) {
            s  += __shfl_down_sync(0xffffffffu, s,  o);
            ss += __shfl_down_sync(0xffffffffu, ss, o);
        }
        if (tid == 0) { red[0][0] = s; red[1][0] = ss; }
    }
    __syncthreads();
    float mean = red[0][0] * (1.f / D_);
    float var  = red[1][0] * (1.f / D_) - mean * mean;
    float rstd = rsqrtf(var + 1e-5f);
    float4 gv = *(const float4*)(g + c);
    float4 bv = *(const float4*)(b + c);
    float4 ov;
    ov.x = (xv.x - mean) * rstd * gv.x + bv.x;
    ov.y = (xv.y - mean) * rstd * gv.y + bv.y;
    ov.z = (xv.z - mean) * rstd * gv.z + bv.z;
    ov.w = (xv.w - mean) * rstd * gv.w + bv.w;
    *(float4*)(out + (size_t)row * D_ + c) = ov;
}

// ---------------- tf32 helpers ----------------
__device__ __forceinline__ unsigned f2tf(float x) {
    unsigned r;
    asm("cvt.rna.tf32.f32 %0, %1;" : "=r"(r) : "f"(x));
    return r;
}

__device__ __forceinline__ void mma_tf32(float4& c,
                                         unsigned a0, unsigned a1, unsigned a2, unsigned a3,
                                         unsigned b0, unsigned b1)
{
    asm volatile("mma.sync.aligned.m16n8k8.row.col.f32.tf32.tf32.f32 "
                 "{%0,%1,%2,%3}, {%4,%5,%6,%7}, {%8,%9}, {%0,%1,%2,%3};"
                 : "+f"(c.x), "+f"(c.y), "+f"(c.z), "+f"(c.w)
                 : "r"(a0), "r"(a1), "r"(a2), "r"(a3), "r"(b0), "r"(b1));
}

// ---------------- tf32 tensor-core GEMM (unchanged from R1) ----------------
#define SPAD 36
template<bool GELU, bool RES>
__global__ void __launch_bounds__(256) mma_gemm(const float* __restrict__ A,
                                                const float* __restrict__ W,
                                                const float* __restrict__ bias,
                                                const float* __restrict__ res,
                                                float* __restrict__ C,
                                                int M, int N, int K)
{
    __shared__ unsigned As[128 * SPAD];
    __shared__ unsigned Bs[128 * SPAD];

    int tid  = threadIdx.x;
    int warp = tid >> 5;
    int lane = tid & 31;
    int g = lane >> 2;
    int t = lane & 3;
    int wm = (warp >> 2) * 64;
    int wn = (warp & 3) * 32;

    int m0 = blockIdx.y * 128;
    int n0 = blockIdx.x * 128;

    int lrow[4], lc4[4];
    #pragma unroll
    for (int u = 0; u < 4; u++) {
        int lin = tid + u * 256;
        lrow[u] = lin >> 3;
        lc4[u]  = (lin & 7) * 4;
    }

    float4 acc[4][4];
    #pragma unroll
    for (int i = 0; i < 4; i++)
        #pragma unroll
        for (int j = 0; j < 4; j++) acc[i][j] = make_float4(0.f, 0.f, 0.f, 0.f);

    float4 stA[4], stB[4];
    #pragma unroll
    for (int u = 0; u < 4; u++) {
        stA[u] = *(const float4*)(A + (size_t)(m0 + lrow[u]) * K + lc4[u]);
        stB[u] = *(const float4*)(W + (size_t)(n0 + lrow[u]) * K + lc4[u]);
    }

    for (int k0 = 0; k0 < K; k0 += 32) {
        #pragma unroll
        for (int u = 0; u < 4; u++) {
            unsigned* ap = &As[lrow[u] * SPAD + lc4[u]];
            ap[0] = f2tf(stA[u].x); ap[1] = f2tf(stA[u].y);
            ap[2] = f2tf(stA[u].z); ap[3] = f2tf(stA[u].w);
            unsigned* bp = &Bs[lrow[u] * SPAD + lc4[u]];
            bp[0] = f2tf(stB[u].x); bp[1] = f2tf(stB[u].y);
            bp[2] = f2tf(stB[u].z); bp[3] = f2tf(stB[u].w);
        }
        __syncthreads();

        if (k0 + 32 < K) {
            #pragma unroll
            for (int u = 0; u < 4; u++) {
                stA[u] = *(const float4*)(A + (size_t)(m0 + lrow[u]) * K + k0 + 32 + lc4[u]);
                stB[u] = *(const float4*)(W + (size_t)(n0 + lrow[u]) * K + k0 + 32 + lc4[u]);
            }
        }

        #pragma unroll
        for (int kk = 0; kk < 32; kk += 8) {
            unsigned af[4][4];
            #pragma unroll
            for (int i = 0; i < 4; i++) {
                int r = wm + 16 * i + g;
                af[i][0] = As[r * SPAD + kk + t];
                af[i][1] = As[(r + 8) * SPAD + kk + t];
                af[i][2] = As[r * SPAD + kk + t + 4];
                af[i][3] = As[(r + 8) * SPAD + kk + t + 4];
            }
            unsigned bf[4][2];
            #pragma unroll
            for (int j = 0; j < 4; j++) {
                int cn = wn + 8 * j + g;
                bf[j][0] = Bs[cn * SPAD + kk + t];
                bf[j][1] = Bs[cn * SPAD + kk + t + 4];
            }
            #pragma unroll
            for (int i = 0; i < 4; i++)
                #pragma unroll
                for (int j = 0; j < 4; j++)
                    mma_tf32(acc[i][j], af[i][0], af[i][1], af[i][2], af[i][3],
                             bf[j][0], bf[j][1]);
        }
        __syncthreads();
    }

    #pragma unroll
    for (int i = 0; i < 4; i++) {
        int r0 = m0 + wm + 16 * i + g;
        int r1 = r0 + 8;
        #pragma unroll
        for (int j = 0; j < 4; j++) {
            int col = n0 + wn + 8 * j + 2 * t;
            float b0 = bias[col], b1 = bias[col + 1];
            float v0 = acc[i][j].x + b0;
            float v1 = acc[i][j].y + b1;
            float v2 = acc[i][j].z + b0;
            float v3 = acc[i][j].w + b1;
            if (RES) {
                const float* rp0 = res + (size_t)r0 * N + col;
                const float* rp1 = res + (size_t)r1 * N + col;
                v0 += rp0[0]; v1 += rp0[1]; v2 += rp1[0]; v3 += rp1[1];
            }
            if (GELU) {
                v0 *= normcdff(v0); v1 *= normcdff(v1);
                v2 *= normcdff(v2); v3 *= normcdff(v3);
            }
            *(float2*)(C + (size_t)r0 * N + col) = make_float2(v0, v1);
            *(float2*)(C + (size_t)r1 * N + col) = make_float2(v2, v3);
        }
    }
}

// ---------------- tf32 tensor-core flash attention ----------------
// CTA: 128 threads (4 warps), 128 query rows (32 per warp), KV tiles of 64.
// Qs[128][FSPAD], Ks[64][FSPAD] (key-major), Vt[64][FSPAD] (dh-major, transposed),
// Ps[128][FSPAD]. All fragment loads hit bank (4g+t)%32 -> conflict-free.
#define FSPAD 68
__global__ void __launch_bounds__(128) flash_mma(const float* __restrict__ q,
                                                 const float* __restrict__ k,
                                                 const float* __restrict__ v,
                                                 float* __restrict__ o)
{
    extern __shared__ unsigned sm_u[];
    unsigned* Qs = sm_u;                    // [128][FSPAD]
    unsigned* Ks = Qs + 128 * FSPAD;        // [64][FSPAD]
    unsigned* Vt = Ks + 64 * FSPAD;         // [64][FSPAD]
    unsigned* Ps = Vt + 64 * FSPAD;         // [128][FSPAD]

    int tid  = threadIdx.x;
    int warp = tid >> 5;
    int lane = tid & 31;
    int g = lane >> 2;
    int t = lane & 3;

    int bh = blockIdx.y;
    int b  = bh >> 4;
    int h  = bh & 15;
    int qt0 = blockIdx.x * 128;
    size_t base = ((size_t)b * T_) * D_ + (size_t)h * DH_;

    // load Q tile (scaled by 1/8), convert tf32
    {
        int rr = tid >> 4;
        int cc = (tid & 15) * 4;
        #pragma unroll
        for (int it = 0; it < 16; it++) {
            int row = rr + it * 8;
            float4 f = *(const float4*)(q + base + (size_t)(qt0 + row) * D_ + cc);
            unsigned* p = &Qs[row * FSPAD + cc];
            p[0] = f2tf(f.x * 0.125f); p[1] = f2tf(f.y * 0.125f);
            p[2] = f2tf(f.z * 0.125f); p[3] = f2tf(f.w * 0.125f);
        }
    }

    // softmax state: rows [g, g+8] per m-block (2 m-blocks per warp)
    float m_i[4] = {-1e30f, -1e30f, -1e30f, -1e30f};
    float l_i[4] = {0.f, 0.f, 0.f, 0.f};
    float4 oacc[2][8];
    #pragma unroll
    for (int mb = 0; mb < 2; mb++)
        #pragma unroll
        for (int nb = 0; nb < 8; nb++) oacc[mb][nb] = make_float4(0.f, 0.f, 0.f, 0.f);

    int r0w = warp * 32;   // warp's first row

    for (int kt0 = 0; kt0 < T_; kt0 += 64) {
        __syncthreads();   // prev iter's reads of Ks/Vt done; Qs ready on first iter
        // load K tile (key-major)
        {
            int rr = tid >> 4;
            int cc = (tid & 15) * 4;
            #pragma unroll
            for (int it = 0; it < 8; it++) {
                int row = rr + it * 8;
                float4 f = *(const float4*)(k + base + (size_t)(kt0 + row) * D_ + cc);
                unsigned* p = &Ks[row * FSPAD + cc];
                p[0] = f2tf(f.x); p[1] = f2tf(f.y); p[2] = f2tf(f.z); p[3] = f2tf(f.w);
            }
        }
        // load V tile transposed -> Vt[dh][key]
        {
            int r  = tid & 63;
            int d0 = (tid >> 6) * 32;
            #pragma unroll
            for (int i = 0; i < 8; i++) {
                float4 f = *(const float4*)(v + base + (size_t)(kt0 + r) * D_ + d0 + 4 * i);
                Vt[(d0 + 4 * i + 0) * FSPAD + r] = f2tf(f.x);
                Vt[(d0 + 4 * i + 1) * FSPAD + r] = f2tf(f.y);
                Vt[(d0 + 4 * i + 2) * FSPAD + r] = f2tf(f.z);
                Vt[(d0 + 4 * i + 3) * FSPAD + r] = f2tf(f.w);
            }
        }
        __syncthreads();

        // S = Q @ K^T : per warp 32x64
        float4 sacc[2][8];
        #pragma unroll
        for (int mb = 0; mb < 2; mb++)
            #pragma unroll
            for (int nb = 0; nb < 8; nb++) sacc[mb][nb] = make_float4(0.f, 0.f, 0.f, 0.f);
        #pragma unroll
        for (int kk = 0; kk < 8; kk++) {
            unsigned a[2][4];
            #pragma unroll
            for (int mb = 0; mb < 2; mb++) {
                int r = r0w + mb * 16 + g;
                a[mb][0] = Qs[r * FSPAD + kk * 8 + t];
                a[mb][1] = Qs[(r + 8) * FSPAD + kk * 8 + t];
                a[mb][2] = Qs[r * FSPAD + kk * 8 + t + 4];
                a[mb][3] = Qs[(r + 8) * FSPAD + kk * 8 + t + 4];
            }
            unsigned bb[8][2];
            #pragma unroll
            for (int nb = 0; nb < 8; nb++) {
                bb[nb][0] = Ks[(nb * 8 + g) * FSPAD + kk * 8 + t];
                bb[nb][1] = Ks[(nb * 8 + g) * FSPAD + kk * 8 + t + 4];
            }
            #pragma unroll
            for (int mb = 0; mb < 2; mb++)
                #pragma unroll
                for (int nb = 0; nb < 8; nb++)
                    mma_tf32(sacc[mb][nb], a[mb][0], a[mb][1], a[mb][2], a[mb][3],
                             bb[nb][0], bb[nb][1]);
        }

        // online softmax on fragments; write P (tf32) to Ps
        #pragma unroll
        for (int mb = 0; mb < 2; mb++) {
            float mx0 = -1e30f, mx1 = -1e30f;
            #pragma unroll
            for (int nb = 0; nb < 8; nb++) {
                mx0 = fmaxf(mx0, fmaxf(sacc[mb][nb].x, sacc[mb][nb].y));
                mx1 = fmaxf(mx1, fmaxf(sacc[mb][nb].z, sacc[mb][nb].w));
            }
            mx0 = fmaxf(mx0, __shfl_xor_sync(0xffffffffu, mx0, 1));
            mx0 = fmaxf(mx0, __shfl_xor_sync(0xffffffffu, mx0, 2));
            mx1 = fmaxf(mx1, __shfl_xor_sync(0xffffffffu, mx1, 1));
            mx1 = fmaxf(mx1, __shfl_xor_sync(0xffffffffu, mx1, 2));

            float mn0 = fmaxf(m_i[2 * mb + 0], mx0);
            float mn1 = fmaxf(m_i[2 * mb + 1], mx1);
            float al0 = __expf(m_i[2 * mb + 0] - mn0);
            float al1 = __expf(m_i[2 * mb + 1] - mn1);
            m_i[2 * mb + 0] = mn0;
            m_i[2 * mb + 1] = mn1;

            float s0 = 0.f, s1 = 0.f;
            int rbase = (r0w + mb * 16 + g) * FSPAD;
            int rbase8 = (r0w + mb * 16 + g + 8) * FSPAD;
            #pragma unroll
            for (int nb = 0; nb < 8; nb++) {
                float p0 = __expf(sacc[mb][nb].x - mn0);
                float p1 = __expf(sacc[mb][nb].y - mn0);
                float p2 = __expf(sacc[mb][nb].z - mn1);
                float p3 = __expf(sacc[mb][nb].w - mn1);
                s0 += p0 + p1; s1 += p2 + p3;
                int cc = nb * 8 + 2 * t;
                Ps[rbase + cc]      = f2tf(p0);
                Ps[rbase + cc + 1]  = f2tf(p1);
                Ps[rbase8 + cc]     = f2tf(p2);
                Ps[rbase8 + cc + 1] = f2tf(p3);
            }
            s0 += __shfl_xor_sync(0xffffffffu, s0, 1);
            s0 += __shfl_xor_sync(0xffffffffu, s0, 2);
            s1 += __shfl_xor_sync(0xffffffffu, s1, 1);
            s1 += __shfl_xor_sync(0xffffffffu, s1, 2);
            l_i[2 * mb + 0] = l_i[2 * mb + 0] * al0 + s0;
            l_i[2 * mb + 1] = l_i[2 * mb + 1] * al1 + s1;

            #pragma unroll
            for (int nb = 0; nb < 8; nb++) {
                oacc[mb][nb].x *= al0; oacc[mb][nb].y *= al0;
                oacc[mb][nb].z *= al1; oacc[mb][nb].w *= al1;
            }
        }
        __syncwarp();   // Ps rows are warp-private; order STS before LDS

        // O += P @ V : per warp 32x64, k = 64 keys
        #pragma unroll
        for (int kk = 0; kk < 8; kk++) {
            unsigned a[2][4];
            #pragma unroll
            for (int mb = 0; mb < 2; mb++) {
                int r = r0w + mb * 16 + g;
                a[mb][0] = Ps[r * FSPAD + kk * 8 + t];
                a[mb][1] = Ps[(r + 8) * FSPAD + kk * 8 + t];
                a[mb][2] = Ps[r * FSPAD + kk * 8 + t + 4];
                a[mb][3] = Ps[(r + 8) * FSPAD + kk * 8 + t + 4];
            }
            unsigned bb[8][2];
            #pragma unroll
            for (int nb = 0; nb < 8; nb++) {
                bb[nb][0] = Vt[(nb * 8 + g) * FSPAD + kk * 8 + t];
                bb[nb][1] = Vt[(nb * 8 + g) * FSPAD + kk * 8 + t + 4];
            }
            #pragma unroll
            for (int mb = 0; mb < 2; mb++)
                #pragma unroll
                for (int nb = 0; nb < 8; nb++)
                    mma_tf32(oacc[mb][nb], a[mb][0], a[mb][1], a[mb][2], a[mb][3],
                             bb[nb][0], bb[nb][1]);
        }
    }

    // epilogue: divide by l, write out
    #pragma unroll
    for (int mb = 0; mb < 2; mb++) {
        float inv0 = 1.f / l_i[2 * mb + 0];
        float inv1 = 1.f / l_i[2 * mb + 1];
        int row0 = qt0 + r0w + mb * 16 + g;
        int row1 = row0 + 8;
        #pragma unroll
        for (int nb = 0; nb < 8; nb++) {
            int cc = nb * 8 + 2 * t;
            *(float2*)(o + base + (size_t)row0 * D_ + cc) =
                make_float2(oacc[mb][nb].x * inv0, oacc[mb][nb].y * inv0);
            *(float2*)(o + base + (size_t)row1 * D_ + cc) =
                make_float2(oacc[mb][nb].z * inv1, oacc[mb][nb].w * inv1);
        }
    }
}

// ---------------- launch ----------------
extern "C" void kernel_launch(void* const* d_in, const int* in_sizes, int n_in,
                              void* d_out, int out_size)
{
    const float* x    = (const float*)d_in[0];
    const float* ln1g = (const float*)d_in[1];
    const float* ln1b = (const float*)d_in[2];
    const float* ln2g = (const float*)d_in[3];
    const float* ln2b = (const float*)d_in[4];
    const float* wq   = (const float*)d_in[5];
    const float* bq   = (const float*)d_in[6];
    const float* wk   = (const float*)d_in[7];
    const float* bk   = (const float*)d_in[8];
    const float* wv   = (const float*)d_in[9];
    const float* bv   = (const float*)d_in[10];
    const float* wo   = (const float*)d_in[11];
    const float* bo   = (const float*)d_in[12];
    const float* w1   = (const float*)d_in[13];
    const float* b1   = (const float*)d_in[14];
    const float* w2   = (const float*)d_in[15];
    const float* b2   = (const float*)d_in[16];
    float* out = (float*)d_out;

    void* p;
    cudaGetSymbolAddress(&p, g_h);   float* h   = (float*)p;
    cudaGetSymbolAddress(&p, g_q);   float* qb  = (float*)p;
    cudaGetSymbolAddress(&p, g_k);   float* kb  = (float*)p;
    cudaGetSymbolAddress(&p, g_v);   float* vb  = (float*)p;
    cudaGetSymbolAddress(&p, g_att); float* att = (float*)p;
    cudaGetSymbolAddress(&p, g_x2);  float* x2  = (float*)p;
    cudaGetSymbolAddress(&p, g_ff);  float* ff  = (float*)p;

    int flash_smem = (128 + 64 + 64 + 128) * FSPAD * (int)sizeof(unsigned);
    cudaFuncSetAttribute(flash_mma, cudaFuncAttributeMaxDynamicSharedMemorySize, flash_smem);

    dim3 gD(D_ / 128, NT / 128);    // (8, 64)
    dim3 gF(FF_ / 128, NT / 128);   // (32, 64)

    ln_k<<<NT, 256>>>(x, ln1g, ln1b, h);
    mma_gemm<false, false><<<gD, 256>>>(h, wq, bq, nullptr, qb, NT, D_, D_);
    mma_gemm<false, false><<<gD, 256>>>(h, wk, bk, nullptr, kb, NT, D_, D_);
    mma_gemm<false, false><<<gD, 256>>>(h, wv, bv, nullptr, vb, NT, D_, D_);
    flash_mma<<<dim3(T_ / 128, B_ * H_), 128, flash_smem>>>(qb, kb, vb, att);
    mma_gemm<false, true><<<gD, 256>>>(att, wo, bo, x, x2, NT, D_, D_);
    ln_k<<<NT, 256>>>(x2, ln2g, ln2b, h);
    mma_gemm<true, false><<<gF, 256>>>(h, w1, b1, nullptr, ff, NT, FF_, D_);
    mma_gemm<false, true><<<gD, 256>>>(ff, w2, b2, x2, out, NT, D_, FF_);
}